// round 8
// baseline (speedup 1.0000x reference)
#include <cuda_runtime.h>

// QuanvLayer closed form:
//   z_i = cos(w_i) * cos(x_i)   (patch elements p00,p01,p10,p11)
//   out[q=0] = z1*z2*z3 ; out[q=1] = z0*z1 ; out[q=2] = z0*z1*z2 ; out[q=3] = z0*z1*z2*z3
//
// x: (128, 3, 128, 128) f32 ; weights: (1,4) f32 ; out: (128, 12, 64, 64) f32
//
// R8: steady-state prefetch pipeline. 592 blocks (exactly 4/SM) x 256 threads,
// each thread handles chunks tid, tid+151552, (tid+303104 if bc<88).
// 151552 = 148*1024 -> next chunk is bc+=148 (constant offset). Loads for the
// next chunk are issued BEFORE computing the current one, keeping the DRAM
// queue continuously fed instead of one burst per warp.

#define B_ 128
#define C_ 3
#define H_ 128
#define W_ 128
#define HH 64
#define WH 64

#define NBLOCKS 592
#define NTHREADS 256
// chunk stride across rounds, in chunks: 151552 = 148 * 1024 -> bc += 148
#define XSTEP ((size_t)148 * H_ * W_)            // input float offset per round
#define OSTEP ((size_t)4 * 148 * HH * WH)        // output float offset per round

__device__ __forceinline__ void quanv_patch4(
    const float4& t0, const float4& t1, const float4& b0, const float4& b1,
    float cw0, float cw1, float cw2, float cw3, float* __restrict__ o)
{
    float top[8] = {t0.x, t0.y, t0.z, t0.w, t1.x, t1.y, t1.z, t1.w};
    float bot[8] = {b0.x, b0.y, b0.z, b0.w, b1.x, b1.y, b1.z, b1.w};
    float o0[4], o1[4], o2[4], o3[4];
    #pragma unroll
    for (int p = 0; p < 4; p++) {
        float z0 = cw0 * __cosf(top[2*p]);
        float z1 = cw1 * __cosf(top[2*p + 1]);
        float z2 = cw2 * __cosf(bot[2*p]);
        float z3 = cw3 * __cosf(bot[2*p + 1]);
        float q1 = z0 * z1;
        float q2 = q1 * z2;
        float q3 = q2 * z3;
        float q0 = z1 * z2 * z3;
        o0[p] = q0; o1[p] = q1; o2[p] = q2; o3[p] = q3;
    }
    *reinterpret_cast<float4*>(o)           = make_float4(o0[0], o0[1], o0[2], o0[3]);
    *reinterpret_cast<float4*>(o + 1*HH*WH) = make_float4(o1[0], o1[1], o1[2], o1[3]);
    *reinterpret_cast<float4*>(o + 2*HH*WH) = make_float4(o2[0], o2[1], o2[2], o2[3]);
    *reinterpret_cast<float4*>(o + 3*HH*WH) = make_float4(o3[0], o3[1], o3[2], o3[3]);
}

__global__ void __launch_bounds__(NTHREADS, 4)
quanv_kernel(const float* __restrict__ x,
             const float* __restrict__ w,
             float* __restrict__ out)
{
    const float cw0 = __cosf(__ldg(w + 0));
    const float cw1 = __cosf(__ldg(w + 1));
    const float cw2 = __cosf(__ldg(w + 2));
    const float cw3 = __cosf(__ldg(w + 3));

    int tid = blockIdx.x * NTHREADS + threadIdx.x;   // [0, 151552)

    // chunk decomposition: tid = (bc*HH + h2)*16 + w8
    int w8 = tid & 15;
    int h2 = (tid >> 4) & (HH - 1);
    int bc = tid >> 10;                              // [0, 148)
    bool heavy = (bc < 88);                          // third chunk exists

    const float* r1 = x + ((size_t)bc * H_ + 2 * h2) * W_ + 8 * w8;
    const float* r2 = r1 + XSTEP;

    // front-batch loads for chunks 1 and 2 (8 LDG.128 in flight)
    const float4 At0 = *reinterpret_cast<const float4*>(r1);
    const float4 At1 = *reinterpret_cast<const float4*>(r1 + 4);
    const float4 Ab0 = *reinterpret_cast<const float4*>(r1 + W_);
    const float4 Ab1 = *reinterpret_cast<const float4*>(r1 + W_ + 4);
    const float4 Bt0 = *reinterpret_cast<const float4*>(r2);
    const float4 Bt1 = *reinterpret_cast<const float4*>(r2 + 4);
    const float4 Bb0 = *reinterpret_cast<const float4*>(r2 + W_);
    const float4 Bb1 = *reinterpret_cast<const float4*>(r2 + W_ + 4);

    float* oA = out + (((size_t)4 * bc) * HH + h2) * WH + 4 * w8;

    // compute chunk 1 while chunk 2 (and soon 3) are in flight
    quanv_patch4(At0, At1, Ab0, Ab1, cw0, cw1, cw2, cw3, oA);

    // prefetch chunk 3 before consuming chunk 2
    float4 Ct0, Ct1, Cb0, Cb1;
    if (heavy) {
        const float* r3 = r2 + XSTEP;
        Ct0 = *reinterpret_cast<const float4*>(r3);
        Ct1 = *reinterpret_cast<const float4*>(r3 + 4);
        Cb0 = *reinterpret_cast<const float4*>(r3 + W_);
        Cb1 = *reinterpret_cast<const float4*>(r3 + W_ + 4);
    }

    quanv_patch4(Bt0, Bt1, Bb0, Bb1, cw0, cw1, cw2, cw3, oA + OSTEP);

    if (heavy) {
        quanv_patch4(Ct0, Ct1, Cb0, Cb1, cw0, cw1, cw2, cw3, oA + 2 * OSTEP);
    }
}

extern "C" void kernel_launch(void* const* d_in, const int* in_sizes, int n_in,
                              void* d_out, int out_size)
{
    const float* x = (const float*)d_in[0];
    const float* w = (const float*)d_in[1];
    if (n_in >= 2 && in_sizes[0] == 4) {
        x = (const float*)d_in[1];
        w = (const float*)d_in[0];
    }
    float* out = (float*)d_out;

    quanv_kernel<<<NBLOCKS, NTHREADS>>>(x, w, out);
}